// round 5
// baseline (speedup 1.0000x reference)
#include <cuda_runtime.h>
#include <cuda_bf16.h>
#include <cstdint>

// Problem shape (fixed by the dataset)
#define B_  32
#define T_  768
#define C_  448
#define E_  256
#define N_  3136          // H*W = 56*56
#define SCALE 0.0625f     // 1/sqrt(E)

#define CHUNK 16
#define PITCH 17              // smem row pitch (odd -> conflict-free)
#define GX 49                 // pixel-groups per batch (blocks in x)
#define CPB 4                 // chunks per block: 49*4*16 = 3136 exact

// -------- device scratch (no allocations allowed) --------
__device__ float g_q[B_ * E_];              // q = text @ q_w^T + q_b
__device__ float g_a[B_ * C_];              // scale * (q[b]^T k_w)[c]
__device__ float g_qkb[B_];                 // scale * q[b].k_b
__device__ float g_Spart[B_ * GX * C_];     // per-group weighted channel sums
__device__ float g_Dpart[B_ * GX];          // per-group exp-sum partials
__device__ float g_pooled[B_ * E_];         // pooled (already /D, +v_b)

// ============================================================
// Kernel 1a: q[b,e] = text[b] . q_w[e] + q_b[e]
// grid (8, B_): block handles 32 e; warp per 4 e.
// ============================================================
__global__ void __launch_bounds__(256) k_q(
    const float* __restrict__ text, const float* __restrict__ q_w,
    const float* __restrict__ q_b)
{
    int slice = blockIdx.x, b = blockIdx.y;
    int tid = threadIdx.x, warp = tid >> 5, lane = tid & 31;
    __shared__ float txt[T_];

    const float4* tsrc = reinterpret_cast<const float4*>(text + (size_t)b * T_);
    for (int j = tid; j < T_ / 4; j += 256)
        reinterpret_cast<float4*>(txt)[j] = tsrc[j];
    __syncthreads();

    int e0 = slice * 32 + warp * 4;
    const float4* tt = reinterpret_cast<const float4*>(txt);
    const float4* w0 = reinterpret_cast<const float4*>(q_w + (size_t)(e0 + 0) * T_);
    const float4* w1 = reinterpret_cast<const float4*>(q_w + (size_t)(e0 + 1) * T_);
    const float4* w2 = reinterpret_cast<const float4*>(q_w + (size_t)(e0 + 2) * T_);
    const float4* w3 = reinterpret_cast<const float4*>(q_w + (size_t)(e0 + 3) * T_);
    float a0 = 0.f, a1 = 0.f, a2 = 0.f, a3 = 0.f;
    #pragma unroll
    for (int it = 0; it < 6; ++it) {          // 6*32*4 = 768 exact
        int j = it * 32 + lane;
        float4 y = tt[j];
        float4 x0 = w0[j], x1 = w1[j], x2 = w2[j], x3 = w3[j];
        a0 += x0.x * y.x + x0.y * y.y + x0.z * y.z + x0.w * y.w;
        a1 += x1.x * y.x + x1.y * y.y + x1.z * y.z + x1.w * y.w;
        a2 += x2.x * y.x + x2.y * y.y + x2.z * y.z + x2.w * y.w;
        a3 += x3.x * y.x + x3.y * y.y + x3.z * y.z + x3.w * y.w;
    }
    #pragma unroll
    for (int o = 16; o > 0; o >>= 1) {
        a0 += __shfl_down_sync(0xffffffffu, a0, o);
        a1 += __shfl_down_sync(0xffffffffu, a1, o);
        a2 += __shfl_down_sync(0xffffffffu, a2, o);
        a3 += __shfl_down_sync(0xffffffffu, a3, o);
    }
    if (lane == 0) {
        g_q[b * E_ + e0 + 0] = a0 + q_b[e0 + 0];
        g_q[b * E_ + e0 + 1] = a1 + q_b[e0 + 1];
        g_q[b * E_ + e0 + 2] = a2 + q_b[e0 + 2];
        g_q[b * E_ + e0 + 3] = a3 + q_b[e0 + 3];
    }
}

// ============================================================
// Kernel 1b: a[b,c] = scale * sum_e q[e] k_w[e,c];  qkb[b].
// ============================================================
__global__ void __launch_bounds__(256) k_a(
    const float* __restrict__ k_w, const float* __restrict__ k_b)
{
    int b = blockIdx.x, tid = threadIdx.x;
    __shared__ float q_sm[E_];
    __shared__ float red[256];

    q_sm[tid] = g_q[b * E_ + tid];
    red[tid] = q_sm[tid] * k_b[tid];
    __syncthreads();
    for (int s = 128; s > 0; s >>= 1) {
        if (tid < s) red[tid] += red[tid + s];
        __syncthreads();
    }
    if (tid == 0) g_qkb[b] = SCALE * red[0];

    // fused dual-c loop: 16 loads in flight
    {
        int c0 = tid, c1 = tid + 256;       // c1 valid iff tid < 192
        float acc0 = 0.f, acc1 = 0.f;
        if (tid < 192) {
            #pragma unroll 8
            for (int e = 0; e < E_; ++e) {
                float qv = q_sm[e];
                acc0 += qv * k_w[e * C_ + c0];
                acc1 += qv * k_w[e * C_ + c1];
            }
            g_a[b * C_ + c1] = SCALE * acc1;
        } else {
            #pragma unroll 8
            for (int e = 0; e < E_; ++e) acc0 += q_sm[e] * k_w[e * C_ + c0];
        }
        g_a[b * C_ + c0] = SCALE * acc0;
    }
}

// ============================================================
// Kernel 2: attention pass with register-prefetch pipelining.
// Block (gx, b) processes CPB chunks of 16 pixels.
// ============================================================
__global__ void __launch_bounds__(256) k_attn_pass(const float* __restrict__ img)
{
    int gx = blockIdx.x, b = blockIdx.y;
    int tid = threadIdx.x;
    int warp = tid >> 5, lane = tid & 31;

    __shared__ float tile[C_ * PITCH];   // 448*17*4 = 30464 B
    __shared__ float a_sm[C_];
    __shared__ float e_sm[CHUNK];
    __shared__ float d_sm[8];

    for (int c = tid; c < C_; c += 256) a_sm[c] = g_a[b * C_ + c];
    float qkb = g_qkb[b];

    const float* base = img + (size_t)b * C_ * N_ + gx * (CPB * CHUNK);

    // precompute the 7 (c, v) pairs this thread loads/stores
    int cc[7], vv[7];
    #pragma unroll
    for (int it = 0; it < 7; ++it) {
        int idx = it * 256 + tid;           // < 1792
        cc[it] = idx >> 2; vv[it] = idx & 3;
    }

    float4 r[7];
    // prefetch chunk 0
    #pragma unroll
    for (int it = 0; it < 7; ++it)
        r[it] = *reinterpret_cast<const float4*>(base + (size_t)cc[it] * N_ + vv[it] * 4);
    // store chunk 0
    #pragma unroll
    for (int it = 0; it < 7; ++it) {
        float* t = tile + cc[it] * PITCH + vv[it] * 4;
        t[0] = r[it].x; t[1] = r[it].y; t[2] = r[it].z; t[3] = r[it].w;
    }
    __syncthreads();

    float sAcc0 = 0.f, sAcc1 = 0.f;   // channels tid and tid+256
    float dAcc = 0.f;                  // per-warp (lane0) exp-sum

    for (int i = 0; i < CPB; ++i) {
        // ---- issue prefetch of next chunk (overlaps phases A/B) ----
        if (i + 1 < CPB) {
            const float* src = base + (i + 1) * CHUNK;
            #pragma unroll
            for (int it = 0; it < 7; ++it)
                r[it] = *reinterpret_cast<const float4*>(src + (size_t)cc[it] * N_ + vv[it] * 4);
        }

        // ---- Phase A: logits. warp w owns pixels 2w, 2w+1 ----
        {
            float p0 = 0.f, p1 = 0.f;
            int px = warp * 2;
            #pragma unroll
            for (int j = 0; j < 14; ++j) {
                int c = j * 32 + lane;
                float av = a_sm[c];
                const float* t = tile + c * PITCH + px;
                p0 += av * t[0];
                p1 += av * t[1];
            }
            #pragma unroll
            for (int o = 16; o > 0; o >>= 1) {
                p0 += __shfl_xor_sync(0xffffffffu, p0, o);
                p1 += __shfl_xor_sync(0xffffffffu, p1, o);
            }
            if (lane == 0) {
                float e0 = __expf(p0 + qkb);
                float e1 = __expf(p1 + qkb);
                e_sm[px] = e0; e_sm[px + 1] = e1;
                dAcc += e0 + e1;
            }
        }
        __syncthreads();   // e_sm ready

        // ---- Phase B: S[c] += sum_j e[j] * x[c,j] ----
        {
            const float* t0 = tile + tid * PITCH;
            float a0 = 0.f, a1 = 0.f;
            if (tid < 192) {
                const float* t1 = tile + (tid + 256) * PITCH;
                #pragma unroll
                for (int j = 0; j < CHUNK; ++j) {
                    float e = e_sm[j];
                    a0 += e * t0[j];
                    a1 += e * t1[j];
                }
            } else {
                #pragma unroll
                for (int j = 0; j < CHUNK; ++j) a0 += e_sm[j] * t0[j];
            }
            sAcc0 += a0; sAcc1 += a1;
        }
        __syncthreads();   // all tile reads done

        // ---- store prefetched chunk ----
        if (i + 1 < CPB) {
            #pragma unroll
            for (int it = 0; it < 7; ++it) {
                float* t = tile + cc[it] * PITCH + vv[it] * 4;
                t[0] = r[it].x; t[1] = r[it].y; t[2] = r[it].z; t[3] = r[it].w;
            }
            __syncthreads();   // tile ready for next iteration
        }
    }

    // ---- write partials ----
    float* Sp = g_Spart + ((size_t)(b * GX + gx)) * C_;
    Sp[tid] = sAcc0;
    if (tid < 192) Sp[tid + 256] = sAcc1;

    if (lane == 0) d_sm[warp] = dAcc;
    __syncthreads();
    if (tid == 0) {
        float d = 0.f;
        #pragma unroll
        for (int w = 0; w < 8; ++w) d += d_sm[w];
        g_Dpart[b * GX + gx] = d;
    }
}

// ============================================================
// Kernel 3: reduce partials, pooled = v_w @ (s/D) + v_b.
// One block per batch.
// ============================================================
__global__ void __launch_bounds__(256) k_pool(
    const float* __restrict__ v_w, const float* __restrict__ v_b)
{
    int b = blockIdx.x, tid = threadIdx.x;
    int warp = tid >> 5, lane = tid & 31;
    __shared__ float s_sm[C_];
    __shared__ float invD_sm;

    for (int c = tid; c < C_; c += 256) {
        const float* Sp = g_Spart + (size_t)b * GX * C_ + c;
        float a0 = 0.f;
        #pragma unroll 7
        for (int g = 0; g < GX; ++g) a0 += Sp[(size_t)g * C_];
        s_sm[c] = a0;
    }
    if (tid < 32) {
        float d = (tid < GX) ? g_Dpart[b * GX + tid] : 0.f;
        if (tid + 32 < GX) d += g_Dpart[b * GX + tid + 32];
        #pragma unroll
        for (int o = 16; o > 0; o >>= 1) d += __shfl_xor_sync(0xffffffffu, d, o);
        if (tid == 0) invD_sm = 1.0f / d;
    }
    __syncthreads();
    float invD = invD_sm;

    // pooled[e]: warp computes pairs (16 trips), lanes coalesced over c
    for (int r = 0; r < 32; r += 2) {
        int e0 = warp * 32 + r, e1 = e0 + 1;
        const float* w0 = v_w + (size_t)e0 * C_;
        const float* w1 = v_w + (size_t)e1 * C_;
        float acc0 = 0.f, acc1 = 0.f;
        #pragma unroll
        for (int it = 0; it < 14; ++it) {
            int c = it * 32 + lane;
            float sv = s_sm[c];
            acc0 += w0[c] * sv;
            acc1 += w1[c] * sv;
        }
        #pragma unroll
        for (int o = 16; o > 0; o >>= 1) {
            acc0 += __shfl_down_sync(0xffffffffu, acc0, o);
            acc1 += __shfl_down_sync(0xffffffffu, acc1, o);
        }
        if (lane == 0) {
            g_pooled[b * E_ + e0] = acc0 * invD + v_b[e0];
            g_pooled[b * E_ + e1] = acc1 * invD + v_b[e1];
        }
    }
}

// ============================================================
// Kernel 4: fused out-projection + residual.
// One block per (b,c): out_bc = o_w[c].pooled[b] + o_b[c];
// img loads issued first so the dot hides under their latency.
// ============================================================
__global__ void __launch_bounds__(256) k_residual(const float* __restrict__ img,
                                                  const float* __restrict__ o_w,
                                                  const float* __restrict__ o_b,
                                                  float* __restrict__ out)
{
    int blk = blockIdx.x;              // 0 .. B_*C_-1
    int b = blk / C_, c = blk - b * C_;
    int tid = threadIdx.x;
    int warp = tid >> 5, lane = tid & 31;

    __shared__ float red[8];
    __shared__ float add_sm;

    const float4* src = reinterpret_cast<const float4*>(img) + (size_t)blk * (N_ / 4);
    float4* dst = reinterpret_cast<float4*>(out) + (size_t)blk * (N_ / 4);

    // issue image loads first (784 float4: 3 per thread + 16-thread tail)
    float4 r0 = src[tid];
    float4 r1 = src[tid + 256];
    float4 r2 = src[tid + 512];
    float4 r3;
    if (tid < 16) r3 = src[tid + 768];

    // out[b,c] dot: one e per thread
    float p = o_w[(size_t)c * E_ + tid] * g_pooled[b * E_ + tid];
    #pragma unroll
    for (int o = 16; o > 0; o >>= 1) p += __shfl_down_sync(0xffffffffu, p, o);
    if (lane == 0) red[warp] = p;
    __syncthreads();
    if (tid == 0) {
        float s = red[0] + red[1] + red[2] + red[3]
                + red[4] + red[5] + red[6] + red[7];
        add_sm = s + o_b[c];
    }
    __syncthreads();
    float add = add_sm;

    r0.x += add; r0.y += add; r0.z += add; r0.w += add;
    r1.x += add; r1.y += add; r1.z += add; r1.w += add;
    r2.x += add; r2.y += add; r2.z += add; r2.w += add;
    dst[tid] = r0;
    dst[tid + 256] = r1;
    dst[tid + 512] = r2;
    if (tid < 16) {
        r3.x += add; r3.y += add; r3.z += add; r3.w += add;
        dst[tid + 768] = r3;
    }
}

// ============================================================
extern "C" void kernel_launch(void* const* d_in, const int* in_sizes, int n_in,
                              void* d_out, int out_size)
{
    const float* text = (const float*)d_in[0];
    const float* img  = (const float*)d_in[1];
    const float* q_w  = (const float*)d_in[2];
    const float* q_b  = (const float*)d_in[3];
    const float* k_w  = (const float*)d_in[4];
    const float* k_b  = (const float*)d_in[5];
    const float* v_w  = (const float*)d_in[6];
    const float* v_b  = (const float*)d_in[7];
    const float* o_w  = (const float*)d_in[8];
    const float* o_b  = (const float*)d_in[9];
    float* out = (float*)d_out;

    k_q<<<dim3(8, B_), 256>>>(text, q_w, q_b);
    k_a<<<B_, 256>>>(k_w, k_b);
    k_attn_pass<<<dim3(GX, B_), 256>>>(img);
    k_pool<<<B_, 256>>>(v_w, v_b);
    k_residual<<<B_ * C_, 256>>>(img, o_w, o_b, out);
}

// round 6
// speedup vs baseline: 1.3275x; 1.3275x over previous
#include <cuda_runtime.h>
#include <cuda_bf16.h>
#include <cstdint>

// Problem shape (fixed by the dataset)
#define B_  32
#define T_  768
#define C_  448
#define E_  256
#define N_  3136          // H*W = 56*56
#define SCALE 0.0625f     // 1/sqrt(E)

#define CHUNK 16
#define PITCH 17              // smem row pitch (odd -> conflict-free)
#define GX 49                 // pixel-groups per batch (blocks in x)
#define CPB 4                 // chunks per block: 49*4*16 = 3136 exact

// -------- device scratch (no allocations allowed) --------
__device__ float g_q[B_ * E_];              // q = text @ q_w^T + q_b
__device__ float g_a[B_ * C_];              // scale * (q[b]^T k_w)[c]
__device__ float g_qkb[B_];                 // scale * q[b].k_b
__device__ float g_Spart[B_ * GX * C_];     // per-group weighted channel sums
__device__ float g_Dpart[B_ * GX];          // per-group exp-sum partials
__device__ float g_pooled[B_ * E_];         // pooled (already /D, +v_b)

// ============================================================
// Kernel 1a: q[b,e] = text[b] . q_w[e] + q_b[e]
// grid (8, B_): block handles 32 e; warp per 4 e.
// ============================================================
__global__ void __launch_bounds__(256) k_q(
    const float* __restrict__ text, const float* __restrict__ q_w,
    const float* __restrict__ q_b)
{
    int slice = blockIdx.x, b = blockIdx.y;
    int tid = threadIdx.x, warp = tid >> 5, lane = tid & 31;
    __shared__ float txt[T_];

    const float4* tsrc = reinterpret_cast<const float4*>(text + (size_t)b * T_);
    for (int j = tid; j < T_ / 4; j += 256)
        reinterpret_cast<float4*>(txt)[j] = tsrc[j];
    __syncthreads();

    int e0 = slice * 32 + warp * 4;
    const float4* tt = reinterpret_cast<const float4*>(txt);
    const float4* w0 = reinterpret_cast<const float4*>(q_w + (size_t)(e0 + 0) * T_);
    const float4* w1 = reinterpret_cast<const float4*>(q_w + (size_t)(e0 + 1) * T_);
    const float4* w2 = reinterpret_cast<const float4*>(q_w + (size_t)(e0 + 2) * T_);
    const float4* w3 = reinterpret_cast<const float4*>(q_w + (size_t)(e0 + 3) * T_);
    float a0 = 0.f, a1 = 0.f, a2 = 0.f, a3 = 0.f;
    #pragma unroll
    for (int it = 0; it < 6; ++it) {          // 6*32*4 = 768 exact
        int j = it * 32 + lane;
        float4 y = tt[j];
        float4 x0 = w0[j], x1 = w1[j], x2 = w2[j], x3 = w3[j];
        a0 += x0.x * y.x + x0.y * y.y + x0.z * y.z + x0.w * y.w;
        a1 += x1.x * y.x + x1.y * y.y + x1.z * y.z + x1.w * y.w;
        a2 += x2.x * y.x + x2.y * y.y + x2.z * y.z + x2.w * y.w;
        a3 += x3.x * y.x + x3.y * y.y + x3.z * y.z + x3.w * y.w;
    }
    #pragma unroll
    for (int o = 16; o > 0; o >>= 1) {
        a0 += __shfl_down_sync(0xffffffffu, a0, o);
        a1 += __shfl_down_sync(0xffffffffu, a1, o);
        a2 += __shfl_down_sync(0xffffffffu, a2, o);
        a3 += __shfl_down_sync(0xffffffffu, a3, o);
    }
    if (lane == 0) {
        g_q[b * E_ + e0 + 0] = a0 + q_b[e0 + 0];
        g_q[b * E_ + e0 + 1] = a1 + q_b[e0 + 1];
        g_q[b * E_ + e0 + 2] = a2 + q_b[e0 + 2];
        g_q[b * E_ + e0 + 3] = a3 + q_b[e0 + 3];
    }
}

// ============================================================
// Kernel 1b: a[b,c] = scale * sum_e q[e] k_w[e,c];  qkb[b].
// ============================================================
__global__ void __launch_bounds__(256) k_a(
    const float* __restrict__ k_w, const float* __restrict__ k_b)
{
    int b = blockIdx.x, tid = threadIdx.x;
    __shared__ float q_sm[E_];
    __shared__ float red[256];

    q_sm[tid] = g_q[b * E_ + tid];
    red[tid] = q_sm[tid] * k_b[tid];
    __syncthreads();
    for (int s = 128; s > 0; s >>= 1) {
        if (tid < s) red[tid] += red[tid + s];
        __syncthreads();
    }
    if (tid == 0) g_qkb[b] = SCALE * red[0];

    // fused dual-c loop: 16 loads in flight
    {
        int c0 = tid, c1 = tid + 256;       // c1 valid iff tid < 192
        float acc0 = 0.f, acc1 = 0.f;
        if (tid < 192) {
            #pragma unroll 8
            for (int e = 0; e < E_; ++e) {
                float qv = q_sm[e];
                acc0 += qv * k_w[e * C_ + c0];
                acc1 += qv * k_w[e * C_ + c1];
            }
            g_a[b * C_ + c1] = SCALE * acc1;
        } else {
            #pragma unroll 8
            for (int e = 0; e < E_; ++e) acc0 += q_sm[e] * k_w[e * C_ + c0];
        }
        g_a[b * C_ + c0] = SCALE * acc0;
    }
}

// ============================================================
// Kernel 2: attention pass with register-prefetch pipelining.
// Block (gx, b) processes CPB chunks of 16 pixels.
// ============================================================
__global__ void __launch_bounds__(256) k_attn_pass(const float* __restrict__ img)
{
    int gx = blockIdx.x, b = blockIdx.y;
    int tid = threadIdx.x;
    int warp = tid >> 5, lane = tid & 31;

    __shared__ float tile[C_ * PITCH];   // 448*17*4 = 30464 B
    __shared__ float a_sm[C_];
    __shared__ float e_sm[CHUNK];
    __shared__ float d_sm[8];

    for (int c = tid; c < C_; c += 256) a_sm[c] = g_a[b * C_ + c];
    float qkb = g_qkb[b];

    const float* base = img + (size_t)b * C_ * N_ + gx * (CPB * CHUNK);

    // precompute the 7 (c, v) pairs this thread loads/stores
    int cc[7], vv[7];
    #pragma unroll
    for (int it = 0; it < 7; ++it) {
        int idx = it * 256 + tid;           // < 1792
        cc[it] = idx >> 2; vv[it] = idx & 3;
    }

    float4 r[7];
    // prefetch chunk 0
    #pragma unroll
    for (int it = 0; it < 7; ++it)
        r[it] = *reinterpret_cast<const float4*>(base + (size_t)cc[it] * N_ + vv[it] * 4);
    // store chunk 0
    #pragma unroll
    for (int it = 0; it < 7; ++it) {
        float* t = tile + cc[it] * PITCH + vv[it] * 4;
        t[0] = r[it].x; t[1] = r[it].y; t[2] = r[it].z; t[3] = r[it].w;
    }
    __syncthreads();

    float sAcc0 = 0.f, sAcc1 = 0.f;   // channels tid and tid+256
    float dAcc = 0.f;                  // per-warp (lane0) exp-sum

    for (int i = 0; i < CPB; ++i) {
        // ---- issue prefetch of next chunk (overlaps phases A/B) ----
        if (i + 1 < CPB) {
            const float* src = base + (i + 1) * CHUNK;
            #pragma unroll
            for (int it = 0; it < 7; ++it)
                r[it] = *reinterpret_cast<const float4*>(src + (size_t)cc[it] * N_ + vv[it] * 4);
        }

        // ---- Phase A: logits. warp w owns pixels 2w, 2w+1 ----
        {
            float p0 = 0.f, p1 = 0.f;
            int px = warp * 2;
            #pragma unroll
            for (int j = 0; j < 14; ++j) {
                int c = j * 32 + lane;
                float av = a_sm[c];
                const float* t = tile + c * PITCH + px;
                p0 += av * t[0];
                p1 += av * t[1];
            }
            #pragma unroll
            for (int o = 16; o > 0; o >>= 1) {
                p0 += __shfl_xor_sync(0xffffffffu, p0, o);
                p1 += __shfl_xor_sync(0xffffffffu, p1, o);
            }
            if (lane == 0) {
                float e0 = __expf(p0 + qkb);
                float e1 = __expf(p1 + qkb);
                e_sm[px] = e0; e_sm[px + 1] = e1;
                dAcc += e0 + e1;
            }
        }
        __syncthreads();   // e_sm ready

        // ---- Phase B: S[c] += sum_j e[j] * x[c,j] ----
        {
            const float* t0 = tile + tid * PITCH;
            float a0 = 0.f, a1 = 0.f;
            if (tid < 192) {
                const float* t1 = tile + (tid + 256) * PITCH;
                #pragma unroll
                for (int j = 0; j < CHUNK; ++j) {
                    float e = e_sm[j];
                    a0 += e * t0[j];
                    a1 += e * t1[j];
                }
            } else {
                #pragma unroll
                for (int j = 0; j < CHUNK; ++j) a0 += e_sm[j] * t0[j];
            }
            sAcc0 += a0; sAcc1 += a1;
        }
        __syncthreads();   // all tile reads done

        // ---- store prefetched chunk ----
        if (i + 1 < CPB) {
            #pragma unroll
            for (int it = 0; it < 7; ++it) {
                float* t = tile + cc[it] * PITCH + vv[it] * 4;
                t[0] = r[it].x; t[1] = r[it].y; t[2] = r[it].z; t[3] = r[it].w;
            }
            __syncthreads();   // tile ready for next iteration
        }
    }

    // ---- write partials ----
    float* Sp = g_Spart + ((size_t)(b * GX + gx)) * C_;
    Sp[tid] = sAcc0;
    if (tid < 192) Sp[tid + 256] = sAcc1;

    if (lane == 0) d_sm[warp] = dAcc;
    __syncthreads();
    if (tid == 0) {
        float d = 0.f;
        #pragma unroll
        for (int w = 0; w < 8; ++w) d += d_sm[w];
        g_Dpart[b * GX + gx] = d;
    }
}

// ============================================================
// Kernel 3: pooled = v_w @ (sum Spart / D) + v_b.
// grid (B_, 8): each block redundantly reduces Spart (L2-hot)
// into smem, then computes a 32-e slice: warp-per-4e, ONE trip.
// ============================================================
__global__ void __launch_bounds__(256) k_pool(
    const float* __restrict__ v_w, const float* __restrict__ v_b)
{
    int b = blockIdx.x, slice = blockIdx.y;
    int tid = threadIdx.x, warp = tid >> 5, lane = tid & 31;
    __shared__ float s_sm[C_];
    __shared__ float invD_sm;

    // Spart reduce: 7 independent accumulators for MLP
    for (int c = tid; c < C_; c += 256) {
        const float* Sp = g_Spart + (size_t)b * GX * C_ + c;
        float a0 = 0.f, a1 = 0.f, a2 = 0.f, a3 = 0.f, a4 = 0.f, a5 = 0.f, a6 = 0.f;
        #pragma unroll
        for (int g = 0; g < GX; g += 7) {       // 49 = 7*7 exact
            a0 += Sp[(size_t)(g + 0) * C_];
            a1 += Sp[(size_t)(g + 1) * C_];
            a2 += Sp[(size_t)(g + 2) * C_];
            a3 += Sp[(size_t)(g + 3) * C_];
            a4 += Sp[(size_t)(g + 4) * C_];
            a5 += Sp[(size_t)(g + 5) * C_];
            a6 += Sp[(size_t)(g + 6) * C_];
        }
        s_sm[c] = ((a0 + a1) + (a2 + a3)) + ((a4 + a5) + a6);
    }
    if (tid < 32) {
        float d = (tid < GX) ? g_Dpart[b * GX + tid] : 0.f;
        if (tid + 32 < GX) d += g_Dpart[b * GX + tid + 32];
        #pragma unroll
        for (int o = 16; o > 0; o >>= 1) d += __shfl_xor_sync(0xffffffffu, d, o);
        if (tid == 0) invD_sm = 1.0f / d;
    }
    __syncthreads();
    float invD = invD_sm;

    // warp computes 4 e's in one trip; lanes coalesced over c
    int e0 = slice * 32 + warp * 4;
    const float* w0 = v_w + (size_t)(e0 + 0) * C_;
    const float* w1 = v_w + (size_t)(e0 + 1) * C_;
    const float* w2 = v_w + (size_t)(e0 + 2) * C_;
    const float* w3 = v_w + (size_t)(e0 + 3) * C_;
    float acc0 = 0.f, acc1 = 0.f, acc2 = 0.f, acc3 = 0.f;
    #pragma unroll
    for (int it = 0; it < 14; ++it) {
        int c = it * 32 + lane;
        float sv = s_sm[c];
        acc0 += w0[c] * sv;
        acc1 += w1[c] * sv;
        acc2 += w2[c] * sv;
        acc3 += w3[c] * sv;
    }
    #pragma unroll
    for (int o = 16; o > 0; o >>= 1) {
        acc0 += __shfl_down_sync(0xffffffffu, acc0, o);
        acc1 += __shfl_down_sync(0xffffffffu, acc1, o);
        acc2 += __shfl_down_sync(0xffffffffu, acc2, o);
        acc3 += __shfl_down_sync(0xffffffffu, acc3, o);
    }
    if (lane == 0) {
        g_pooled[b * E_ + e0 + 0] = acc0 * invD + v_b[e0 + 0];
        g_pooled[b * E_ + e0 + 1] = acc1 * invD + v_b[e0 + 1];
        g_pooled[b * E_ + e0 + 2] = acc2 * invD + v_b[e0 + 2];
        g_pooled[b * E_ + e0 + 3] = acc3 * invD + v_b[e0 + 3];
    }
}

// ============================================================
// Kernel 4: fused out-projection + residual. Barrier-free:
// each warp redundantly computes the 256-dot (L1/L2-hot), so
// the streaming stores never wait on a block barrier.
// ============================================================
__global__ void __launch_bounds__(256) k_residual(const float* __restrict__ img,
                                                  const float* __restrict__ o_w,
                                                  const float* __restrict__ o_b,
                                                  float* __restrict__ out)
{
    int blk = blockIdx.x;              // 0 .. B_*C_-1
    int b = blk / C_, c = blk - b * C_;
    int tid = threadIdx.x, lane = tid & 31;

    const float4* src = reinterpret_cast<const float4*>(img) + (size_t)blk * (N_ / 4);
    float4* dst = reinterpret_cast<float4*>(out) + (size_t)blk * (N_ / 4);

    // issue image loads first (784 float4: 3 per thread + 16-thread tail)
    float4 r0 = src[tid];
    float4 r1 = src[tid + 256];
    float4 r2 = src[tid + 512];
    float4 r3;
    if (tid < 16) r3 = src[tid + 768];

    // per-warp dot over e (o_w row + pooled row are cache-hot)
    const float* wr = o_w + (size_t)c * E_;
    const float* pl = g_pooled + b * E_;
    float p = 0.f;
    #pragma unroll
    for (int it = 0; it < 8; ++it) {
        int e = it * 32 + lane;
        p += wr[e] * pl[e];
    }
    #pragma unroll
    for (int o = 16; o > 0; o >>= 1) p += __shfl_xor_sync(0xffffffffu, p, o);
    float add = p + __ldg(&o_b[c]);

    r0.x += add; r0.y += add; r0.z += add; r0.w += add;
    r1.x += add; r1.y += add; r1.z += add; r1.w += add;
    r2.x += add; r2.y += add; r2.z += add; r2.w += add;
    dst[tid] = r0;
    dst[tid + 256] = r1;
    dst[tid + 512] = r2;
    if (tid < 16) {
        r3.x += add; r3.y += add; r3.z += add; r3.w += add;
        dst[tid + 768] = r3;
    }
}

// ============================================================
extern "C" void kernel_launch(void* const* d_in, const int* in_sizes, int n_in,
                              void* d_out, int out_size)
{
    const float* text = (const float*)d_in[0];
    const float* img  = (const float*)d_in[1];
    const float* q_w  = (const float*)d_in[2];
    const float* q_b  = (const float*)d_in[3];
    const float* k_w  = (const float*)d_in[4];
    const float* k_b  = (const float*)d_in[5];
    const float* v_w  = (const float*)d_in[6];
    const float* v_b  = (const float*)d_in[7];
    const float* o_w  = (const float*)d_in[8];
    const float* o_b  = (const float*)d_in[9];
    float* out = (float*)d_out;

    k_q<<<dim3(8, B_), 256>>>(text, q_w, q_b);
    k_a<<<B_, 256>>>(k_w, k_b);
    k_attn_pass<<<dim3(GX, B_), 256>>>(img);
    k_pool<<<dim3(B_, 8), 256>>>(v_w, v_b);
    k_residual<<<B_ * C_, 256>>>(img, o_w, o_b, out);
}

// round 7
// speedup vs baseline: 1.5168x; 1.1426x over previous
#include <cuda_runtime.h>
#include <cuda_bf16.h>
#include <cstdint>

// Problem shape (fixed by the dataset)
#define B_  32
#define T_  768
#define C_  448
#define E_  256
#define N_  3136          // H*W = 56*56
#define SCALE 0.0625f     // 1/sqrt(E)

#define CHUNK 16
#define GX 49                 // pixel-groups per batch (blocks in x)
#define CPB 4                 // chunks per block: 49*4*16 = 3136 exact

// -------- device scratch (no allocations allowed) --------
__device__ float g_q[B_ * E_];       // q = text @ q_w^T + q_b
__device__ float g_a[B_ * C_];       // scale * (q[b]^T k_w)[c]
__device__ float g_qkb[B_];          // scale * q[b].k_b
__device__ float g_S[B_ * C_];       // attention-weighted channel sums (atomic)
__device__ float g_D[B_];            // exp-sum (atomic)
__device__ float g_pooled[B_ * E_];  // pooled (already /D, +v_b)

// ============================================================
// Kernel 1a: q[b,e] = text[b] . q_w[e] + q_b[e]
// grid (8, B_): block handles 32 e; warp per 4 e.
// ============================================================
__global__ void __launch_bounds__(256) k_q(
    const float* __restrict__ text, const float* __restrict__ q_w,
    const float* __restrict__ q_b)
{
    int slice = blockIdx.x, b = blockIdx.y;
    int tid = threadIdx.x, warp = tid >> 5, lane = tid & 31;
    __shared__ float txt[T_];

    const float4* tsrc = reinterpret_cast<const float4*>(text + (size_t)b * T_);
    for (int j = tid; j < T_ / 4; j += 256)
        reinterpret_cast<float4*>(txt)[j] = tsrc[j];
    __syncthreads();

    int e0 = slice * 32 + warp * 4;
    const float4* tt = reinterpret_cast<const float4*>(txt);
    const float4* w0 = reinterpret_cast<const float4*>(q_w + (size_t)(e0 + 0) * T_);
    const float4* w1 = reinterpret_cast<const float4*>(q_w + (size_t)(e0 + 1) * T_);
    const float4* w2 = reinterpret_cast<const float4*>(q_w + (size_t)(e0 + 2) * T_);
    const float4* w3 = reinterpret_cast<const float4*>(q_w + (size_t)(e0 + 3) * T_);
    float a0 = 0.f, a1 = 0.f, a2 = 0.f, a3 = 0.f;
    #pragma unroll
    for (int it = 0; it < 6; ++it) {          // 6*32*4 = 768 exact
        int j = it * 32 + lane;
        float4 y = tt[j];
        float4 x0 = w0[j], x1 = w1[j], x2 = w2[j], x3 = w3[j];
        a0 += x0.x * y.x + x0.y * y.y + x0.z * y.z + x0.w * y.w;
        a1 += x1.x * y.x + x1.y * y.y + x1.z * y.z + x1.w * y.w;
        a2 += x2.x * y.x + x2.y * y.y + x2.z * y.z + x2.w * y.w;
        a3 += x3.x * y.x + x3.y * y.y + x3.z * y.z + x3.w * y.w;
    }
    #pragma unroll
    for (int o = 16; o > 0; o >>= 1) {
        a0 += __shfl_down_sync(0xffffffffu, a0, o);
        a1 += __shfl_down_sync(0xffffffffu, a1, o);
        a2 += __shfl_down_sync(0xffffffffu, a2, o);
        a3 += __shfl_down_sync(0xffffffffu, a3, o);
    }
    if (lane == 0) {
        g_q[b * E_ + e0 + 0] = a0 + q_b[e0 + 0];
        g_q[b * E_ + e0 + 1] = a1 + q_b[e0 + 1];
        g_q[b * E_ + e0 + 2] = a2 + q_b[e0 + 2];
        g_q[b * E_ + e0 + 3] = a3 + q_b[e0 + 3];
    }
}

// ============================================================
// Kernel 1b: a[b,c] = scale * sum_e q[e] k_w[e,c];  qkb[b].
// Also zeroes g_S[b,:] and g_D[b] for this graph replay.
// ============================================================
__global__ void __launch_bounds__(256) k_a(
    const float* __restrict__ k_w, const float* __restrict__ k_b)
{
    int b = blockIdx.x, tid = threadIdx.x;
    __shared__ float q_sm[E_];
    __shared__ float red[256];

    // zero accumulators for this replay
    g_S[b * C_ + tid] = 0.f;
    if (tid < C_ - 256) g_S[b * C_ + 256 + tid] = 0.f;
    if (tid == 0) g_D[b] = 0.f;

    q_sm[tid] = g_q[b * E_ + tid];
    red[tid] = q_sm[tid] * k_b[tid];
    __syncthreads();
    for (int s = 128; s > 0; s >>= 1) {
        if (tid < s) red[tid] += red[tid + s];
        __syncthreads();
    }
    if (tid == 0) g_qkb[b] = SCALE * red[0];

    // fused dual-c loop: 16 loads in flight
    {
        int c0 = tid, c1 = tid + 256;       // c1 valid iff tid < 192
        float acc0 = 0.f, acc1 = 0.f;
        if (tid < 192) {
            #pragma unroll 8
            for (int e = 0; e < E_; ++e) {
                float qv = q_sm[e];
                acc0 += qv * k_w[e * C_ + c0];
                acc1 += qv * k_w[e * C_ + c1];
            }
            g_a[b * C_ + c1] = SCALE * acc1;
        } else {
            #pragma unroll 8
            for (int e = 0; e < E_; ++e) acc0 += q_sm[e] * k_w[e * C_ + c0];
        }
        g_a[b * C_ + c0] = SCALE * acc0;
    }
}

// ============================================================
// Kernel 2: all-register attention pass.
// Thread layout: v = tid&3 (pixel quarter), k = tid>>2;
// thread owns channels c_it = it*64+k (it=0..6), pixels v*4..v*4+3.
// Per chunk: 7 float4 loads -> partial logits (28 FMA) ->
// xor-shuffle (lanes sharing v) -> 16-thread exp -> phase B (28 FMA).
// Results accumulated in registers, flushed via atomicAdd.
// ============================================================
__global__ void __launch_bounds__(256) k_attn_pass(const float* __restrict__ img)
{
    int gx = blockIdx.x, b = blockIdx.y;
    int tid = threadIdx.x;
    int warp = tid >> 5, lane = tid & 31;
    int v = tid & 3, k = tid >> 2;

    __shared__ float a_sm[C_];
    __shared__ float red_s[128];        // [warp][16] partial logits
    __shared__ float e_sm[CHUNK];

    for (int c = tid; c < C_; c += 256) a_sm[c] = g_a[b * C_ + c];
    float qkb = g_qkb[b];
    __syncthreads();

    // per-thread a values for its 7 channels
    float aq[7];
    #pragma unroll
    for (int it = 0; it < 7; ++it) aq[it] = a_sm[it * 64 + k];

    // base pointer: (b, channel k, pixel gx*64 + v*4)
    const float* base = img + ((size_t)b * C_ + k) * N_ + gx * (CPB * CHUNK) + v * 4;

    float4 rA[7], rB[7];
    #pragma unroll
    for (int it = 0; it < 7; ++it)
        rA[it] = *reinterpret_cast<const float4*>(base + (size_t)(it * 64) * N_);

    float sAcc[7];
    #pragma unroll
    for (int it = 0; it < 7; ++it) sAcc[it] = 0.f;
    float dAcc = 0.f;                    // only meaningful on tid<16

    #pragma unroll
    for (int i = 0; i < CPB; ++i) {
        float4* rc = (i & 1) ? rB : rA;
        float4* rn = (i & 1) ? rA : rB;

        // ---- phase A partials from registers (28 FMA) ----
        float plx = 0.f, ply = 0.f, plz = 0.f, plw = 0.f;
        #pragma unroll
        for (int it = 0; it < 7; ++it) {
            float a = aq[it];
            plx += a * rc[it].x; ply += a * rc[it].y;
            plz += a * rc[it].z; plw += a * rc[it].w;
        }

        // ---- prefetch next chunk (hides under shuffles/barriers) ----
        if (i + 1 < CPB) {
            const float* src = base + (i + 1) * CHUNK;
            #pragma unroll
            for (int it = 0; it < 7; ++it)
                rn[it] = *reinterpret_cast<const float4*>(src + (size_t)(it * 64) * N_);
        }

        // ---- reduce partials over lanes sharing v (strides 4,8,16) ----
        #pragma unroll
        for (int m = 4; m <= 16; m <<= 1) {
            plx += __shfl_xor_sync(0xffffffffu, plx, m);
            ply += __shfl_xor_sync(0xffffffffu, ply, m);
            plz += __shfl_xor_sync(0xffffffffu, plz, m);
            plw += __shfl_xor_sync(0xffffffffu, plw, m);
        }
        if (lane < 4) {      // lane == v for lanes 0..3
            float4 p4 = make_float4(plx, ply, plz, plw);
            reinterpret_cast<float4*>(red_s)[warp * 4 + lane] = p4;
        }
        __syncthreads();

        // ---- exp over 16 pixels ----
        if (tid < 16) {
            float lg = 0.f;
            #pragma unroll
            for (int w = 0; w < 8; ++w) lg += red_s[w * 16 + tid];
            float e = __expf(lg + qkb);
            e_sm[tid] = e;
            dAcc += e;
        }
        __syncthreads();

        // ---- phase B from registers (28 FMA) ----
        float4 e4 = reinterpret_cast<const float4*>(e_sm)[v];
        #pragma unroll
        for (int it = 0; it < 7; ++it)
            sAcc[it] += rc[it].x * e4.x + rc[it].y * e4.y
                      + rc[it].z * e4.z + rc[it].w * e4.w;
    }

    // ---- flush: reduce sAcc over the 4-lane group, atomicAdd ----
    #pragma unroll
    for (int it = 0; it < 7; ++it) {
        float s = sAcc[it];
        s += __shfl_xor_sync(0xffffffffu, s, 1);
        s += __shfl_xor_sync(0xffffffffu, s, 2);
        if (v == 0) atomicAdd(&g_S[b * C_ + it * 64 + k], s);
    }
    if (warp == 0) {   // dAcc nonzero only on lanes 0..15
        float d = dAcc;
        #pragma unroll
        for (int o = 16; o > 0; o >>= 1) d += __shfl_xor_sync(0xffffffffu, d, o);
        if (lane == 0) atomicAdd(&g_D[b], d);
    }
}

// ============================================================
// Kernel 3: pooled = v_w @ (g_S/D) + v_b.
// grid (B_, 8): warp-per-4e, one trip; g_S is tiny & L2-hot.
// ============================================================
__global__ void __launch_bounds__(256) k_pool(
    const float* __restrict__ v_w, const float* __restrict__ v_b)
{
    int b = blockIdx.x, slice = blockIdx.y;
    int tid = threadIdx.x, warp = tid >> 5, lane = tid & 31;
    __shared__ float s_sm[C_];
    __shared__ float invD_sm;

    s_sm[tid] = g_S[b * C_ + tid];
    if (tid < C_ - 256) s_sm[tid + 256] = g_S[b * C_ + tid + 256];
    if (tid == 0) invD_sm = 1.0f / g_D[b];
    __syncthreads();
    float invD = invD_sm;

    int e0 = slice * 32 + warp * 4;
    const float* w0 = v_w + (size_t)(e0 + 0) * C_;
    const float* w1 = v_w + (size_t)(e0 + 1) * C_;
    const float* w2 = v_w + (size_t)(e0 + 2) * C_;
    const float* w3 = v_w + (size_t)(e0 + 3) * C_;
    float acc0 = 0.f, acc1 = 0.f, acc2 = 0.f, acc3 = 0.f;
    #pragma unroll
    for (int it = 0; it < 14; ++it) {
        int c = it * 32 + lane;
        float sv = s_sm[c];
        acc0 += w0[c] * sv;
        acc1 += w1[c] * sv;
        acc2 += w2[c] * sv;
        acc3 += w3[c] * sv;
    }
    #pragma unroll
    for (int o = 16; o > 0; o >>= 1) {
        acc0 += __shfl_down_sync(0xffffffffu, acc0, o);
        acc1 += __shfl_down_sync(0xffffffffu, acc1, o);
        acc2 += __shfl_down_sync(0xffffffffu, acc2, o);
        acc3 += __shfl_down_sync(0xffffffffu, acc3, o);
    }
    if (lane == 0) {
        g_pooled[b * E_ + e0 + 0] = acc0 * invD + v_b[e0 + 0];
        g_pooled[b * E_ + e0 + 1] = acc1 * invD + v_b[e0 + 1];
        g_pooled[b * E_ + e0 + 2] = acc2 * invD + v_b[e0 + 2];
        g_pooled[b * E_ + e0 + 3] = acc3 * invD + v_b[e0 + 3];
    }
}

// ============================================================
// Kernel 4: fused out-projection + residual. Barrier-free:
// each warp redundantly computes the 256-dot (L1/L2-hot).
// ============================================================
__global__ void __launch_bounds__(256) k_residual(const float* __restrict__ img,
                                                  const float* __restrict__ o_w,
                                                  const float* __restrict__ o_b,
                                                  float* __restrict__ out)
{
    int blk = blockIdx.x;              // 0 .. B_*C_-1
    int b = blk / C_, c = blk - b * C_;
    int tid = threadIdx.x, lane = tid & 31;

    const float4* src = reinterpret_cast<const float4*>(img) + (size_t)blk * (N_ / 4);
    float4* dst = reinterpret_cast<float4*>(out) + (size_t)blk * (N_ / 4);

    // issue image loads first (784 float4: 3 per thread + 16-thread tail)
    float4 r0 = src[tid];
    float4 r1 = src[tid + 256];
    float4 r2 = src[tid + 512];
    float4 r3;
    if (tid < 16) r3 = src[tid + 768];

    // per-warp dot over e (o_w row + pooled row are cache-hot)
    const float* wr = o_w + (size_t)c * E_;
    const float* pl = g_pooled + b * E_;
    float p = 0.f;
    #pragma unroll
    for (int it = 0; it < 8; ++it) {
        int e = it * 32 + lane;
        p += wr[e] * pl[e];
    }
    #pragma unroll
    for (int o = 16; o > 0; o >>= 1) p += __shfl_xor_sync(0xffffffffu, p, o);
    float add = p + __ldg(&o_b[c]);

    r0.x += add; r0.y += add; r0.z += add; r0.w += add;
    r1.x += add; r1.y += add; r1.z += add; r1.w += add;
    r2.x += add; r2.y += add; r2.z += add; r2.w += add;
    dst[tid] = r0;
    dst[tid + 256] = r1;
    dst[tid + 512] = r2;
    if (tid < 16) {
        r3.x += add; r3.y += add; r3.z += add; r3.w += add;
        dst[tid + 768] = r3;
    }
}

// ============================================================
extern "C" void kernel_launch(void* const* d_in, const int* in_sizes, int n_in,
                              void* d_out, int out_size)
{
    const float* text = (const float*)d_in[0];
    const float* img  = (const float*)d_in[1];
    const float* q_w  = (const float*)d_in[2];
    const float* q_b  = (const float*)d_in[3];
    const float* k_w  = (const float*)d_in[4];
    const float* k_b  = (const float*)d_in[5];
    const float* v_w  = (const float*)d_in[6];
    const float* v_b  = (const float*)d_in[7];
    const float* o_w  = (const float*)d_in[8];
    const float* o_b  = (const float*)d_in[9];
    float* out = (float*)d_out;

    k_q<<<dim3(8, B_), 256>>>(text, q_w, q_b);
    k_a<<<B_, 256>>>(k_w, k_b);
    k_attn_pass<<<dim3(GX, B_), 256>>>(img);
    k_pool<<<dim3(B_, 8), 256>>>(v_w, v_b);
    k_residual<<<B_ * C_, 256>>>(img, o_w, o_b, out);
}

// round 8
// speedup vs baseline: 1.7817x; 1.1746x over previous
#include <cuda_runtime.h>
#include <cuda_bf16.h>
#include <cstdint>

// Problem shape (fixed by the dataset)
#define B_  32
#define T_  768
#define C_  448
#define E_  256
#define N_  3136          // H*W = 56*56
#define SCALE 0.0625f     // 1/sqrt(E)

#define CHUNK 16
#define GX 98                 // pixel-groups per batch (blocks in x)
#define CPB 2                 // chunks per block: 98*2*16 = 3136 exact

// -------- device scratch (no allocations allowed) --------
__device__ float g_q[B_ * E_];       // q = text @ q_w^T + q_b
__device__ float g_a[B_ * C_];       // scale * (q[b]^T k_w)[c]
__device__ float g_qkb[B_];          // scale * q[b].k_b
__device__ float g_S[B_ * C_];       // attention-weighted channel sums (atomic)
__device__ float g_D[B_];            // exp-sum (atomic)
__device__ float g_pooled[B_ * E_];  // pooled (already /D, +v_b)

// ============================================================
// Kernel 1a: q[b,e] = text[b] . q_w[e] + q_b[e]
// grid (8, B_): block handles 32 e; warp per 4 e.
// ============================================================
__global__ void __launch_bounds__(256) k_q(
    const float* __restrict__ text, const float* __restrict__ q_w,
    const float* __restrict__ q_b)
{
    int slice = blockIdx.x, b = blockIdx.y;
    int tid = threadIdx.x, warp = tid >> 5, lane = tid & 31;
    __shared__ float txt[T_];

    const float4* tsrc = reinterpret_cast<const float4*>(text + (size_t)b * T_);
    for (int j = tid; j < T_ / 4; j += 256)
        reinterpret_cast<float4*>(txt)[j] = tsrc[j];
    __syncthreads();

    int e0 = slice * 32 + warp * 4;
    const float4* tt = reinterpret_cast<const float4*>(txt);
    const float4* w0 = reinterpret_cast<const float4*>(q_w + (size_t)(e0 + 0) * T_);
    const float4* w1 = reinterpret_cast<const float4*>(q_w + (size_t)(e0 + 1) * T_);
    const float4* w2 = reinterpret_cast<const float4*>(q_w + (size_t)(e0 + 2) * T_);
    const float4* w3 = reinterpret_cast<const float4*>(q_w + (size_t)(e0 + 3) * T_);
    float a0 = 0.f, a1 = 0.f, a2 = 0.f, a3 = 0.f;
    #pragma unroll
    for (int it = 0; it < 6; ++it) {          // 6*32*4 = 768 exact
        int j = it * 32 + lane;
        float4 y = tt[j];
        float4 x0 = w0[j], x1 = w1[j], x2 = w2[j], x3 = w3[j];
        a0 += x0.x * y.x + x0.y * y.y + x0.z * y.z + x0.w * y.w;
        a1 += x1.x * y.x + x1.y * y.y + x1.z * y.z + x1.w * y.w;
        a2 += x2.x * y.x + x2.y * y.y + x2.z * y.z + x2.w * y.w;
        a3 += x3.x * y.x + x3.y * y.y + x3.z * y.z + x3.w * y.w;
    }
    #pragma unroll
    for (int o = 16; o > 0; o >>= 1) {
        a0 += __shfl_down_sync(0xffffffffu, a0, o);
        a1 += __shfl_down_sync(0xffffffffu, a1, o);
        a2 += __shfl_down_sync(0xffffffffu, a2, o);
        a3 += __shfl_down_sync(0xffffffffu, a3, o);
    }
    if (lane == 0) {
        g_q[b * E_ + e0 + 0] = a0 + q_b[e0 + 0];
        g_q[b * E_ + e0 + 1] = a1 + q_b[e0 + 1];
        g_q[b * E_ + e0 + 2] = a2 + q_b[e0 + 2];
        g_q[b * E_ + e0 + 3] = a3 + q_b[e0 + 3];
    }
}

// ============================================================
// Kernel 1b: a[b,c] = scale * sum_e q[e] k_w[e,c];  qkb[b].
// Also zeroes g_S[b,:] and g_D[b] for this graph replay.
// ============================================================
__global__ void __launch_bounds__(256) k_a(
    const float* __restrict__ k_w, const float* __restrict__ k_b)
{
    int b = blockIdx.x, tid = threadIdx.x;
    __shared__ float q_sm[E_];
    __shared__ float red[256];

    // zero accumulators for this replay
    g_S[b * C_ + tid] = 0.f;
    if (tid < C_ - 256) g_S[b * C_ + 256 + tid] = 0.f;
    if (tid == 0) g_D[b] = 0.f;

    q_sm[tid] = g_q[b * E_ + tid];
    red[tid] = q_sm[tid] * k_b[tid];
    __syncthreads();
    for (int s = 128; s > 0; s >>= 1) {
        if (tid < s) red[tid] += red[tid + s];
        __syncthreads();
    }
    if (tid == 0) g_qkb[b] = SCALE * red[0];

    // fused dual-c loop: 32 loads in flight
    {
        int c0 = tid, c1 = tid + 256;       // c1 valid iff tid < 192
        float acc0 = 0.f, acc1 = 0.f;
        if (tid < 192) {
            #pragma unroll 16
            for (int e = 0; e < E_; ++e) {
                float qv = q_sm[e];
                acc0 += qv * k_w[e * C_ + c0];
                acc1 += qv * k_w[e * C_ + c1];
            }
            g_a[b * C_ + c1] = SCALE * acc1;
        } else {
            #pragma unroll 16
            for (int e = 0; e < E_; ++e) acc0 += q_sm[e] * k_w[e * C_ + c0];
        }
        g_a[b * C_ + c0] = SCALE * acc0;
    }
}

// ============================================================
// Kernel 2: all-register attention pass.
// Thread layout: v = tid&3 (pixel quarter), k = tid>>2;
// thread owns channels c_it = it*64+k (it=0..6), pixels v*4..v*4+3.
// Streaming (.cs) loads: img has no reuse and exceeds L2.
// ============================================================
__global__ void __launch_bounds__(256) k_attn_pass(const float* __restrict__ img)
{
    int gx = blockIdx.x, b = blockIdx.y;
    int tid = threadIdx.x;
    int warp = tid >> 5, lane = tid & 31;
    int v = tid & 3, k = tid >> 2;

    __shared__ float a_sm[C_];
    __shared__ float red_s[128];        // [warp][16] partial logits
    __shared__ float e_sm[CHUNK];

    for (int c = tid; c < C_; c += 256) a_sm[c] = g_a[b * C_ + c];
    float qkb = g_qkb[b];
    __syncthreads();

    // per-thread a values for its 7 channels
    float aq[7];
    #pragma unroll
    for (int it = 0; it < 7; ++it) aq[it] = a_sm[it * 64 + k];

    // base pointer: (b, channel k, pixel gx*(CPB*16) + v*4)
    const float* base = img + ((size_t)b * C_ + k) * N_ + gx * (CPB * CHUNK) + v * 4;

    float4 rA[7], rB[7];
    #pragma unroll
    for (int it = 0; it < 7; ++it)
        rA[it] = __ldcs(reinterpret_cast<const float4*>(base + (size_t)(it * 64) * N_));

    float sAcc[7];
    #pragma unroll
    for (int it = 0; it < 7; ++it) sAcc[it] = 0.f;
    float dAcc = 0.f;                    // only meaningful on tid<16

    #pragma unroll
    for (int i = 0; i < CPB; ++i) {
        float4* rc = (i & 1) ? rB : rA;
        float4* rn = (i & 1) ? rA : rB;

        // ---- phase A partials from registers (28 FMA) ----
        float plx = 0.f, ply = 0.f, plz = 0.f, plw = 0.f;
        #pragma unroll
        for (int it = 0; it < 7; ++it) {
            float a = aq[it];
            plx += a * rc[it].x; ply += a * rc[it].y;
            plz += a * rc[it].z; plw += a * rc[it].w;
        }

        // ---- prefetch next chunk (hides under shuffles/barriers) ----
        if (i + 1 < CPB) {
            const float* src = base + (i + 1) * CHUNK;
            #pragma unroll
            for (int it = 0; it < 7; ++it)
                rn[it] = __ldcs(reinterpret_cast<const float4*>(src + (size_t)(it * 64) * N_));
        }

        // ---- reduce partials over lanes sharing v (strides 4,8,16) ----
        #pragma unroll
        for (int m = 4; m <= 16; m <<= 1) {
            plx += __shfl_xor_sync(0xffffffffu, plx, m);
            ply += __shfl_xor_sync(0xffffffffu, ply, m);
            plz += __shfl_xor_sync(0xffffffffu, plz, m);
            plw += __shfl_xor_sync(0xffffffffu, plw, m);
        }
        if (lane < 4) {      // lane == v for lanes 0..3
            float4 p4 = make_float4(plx, ply, plz, plw);
            reinterpret_cast<float4*>(red_s)[warp * 4 + lane] = p4;
        }
        __syncthreads();

        // ---- exp over 16 pixels ----
        if (tid < 16) {
            float lg = 0.f;
            #pragma unroll
            for (int w = 0; w < 8; ++w) lg += red_s[w * 16 + tid];
            float e = __expf(lg + qkb);
            e_sm[tid] = e;
            dAcc += e;
        }
        __syncthreads();

        // ---- phase B from registers (28 FMA) ----
        float4 e4 = reinterpret_cast<const float4*>(e_sm)[v];
        #pragma unroll
        for (int it = 0; it < 7; ++it)
            sAcc[it] += rc[it].x * e4.x + rc[it].y * e4.y
                      + rc[it].z * e4.z + rc[it].w * e4.w;
    }

    // ---- flush: reduce sAcc over the 4-lane group, atomicAdd ----
    #pragma unroll
    for (int it = 0; it < 7; ++it) {
        float s = sAcc[it];
        s += __shfl_xor_sync(0xffffffffu, s, 1);
        s += __shfl_xor_sync(0xffffffffu, s, 2);
        if (v == 0) atomicAdd(&g_S[b * C_ + it * 64 + k], s);
    }
    if (warp == 0) {   // dAcc nonzero only on lanes 0..15
        float d = dAcc;
        #pragma unroll
        for (int o = 16; o > 0; o >>= 1) d += __shfl_xor_sync(0xffffffffu, d, o);
        if (lane == 0) atomicAdd(&g_D[b], d);
    }
}

// ============================================================
// Kernel 3: pooled = v_w @ (g_S/D) + v_b.
// grid (B_, 8): warp-per-4e, one trip; g_S is tiny & L2-hot.
// ============================================================
__global__ void __launch_bounds__(256) k_pool(
    const float* __restrict__ v_w, const float* __restrict__ v_b)
{
    int b = blockIdx.x, slice = blockIdx.y;
    int tid = threadIdx.x, warp = tid >> 5, lane = tid & 31;
    __shared__ float s_sm[C_];
    __shared__ float invD_sm;

    s_sm[tid] = g_S[b * C_ + tid];
    if (tid < C_ - 256) s_sm[tid + 256] = g_S[b * C_ + tid + 256];
    if (tid == 0) invD_sm = 1.0f / g_D[b];
    __syncthreads();
    float invD = invD_sm;

    int e0 = slice * 32 + warp * 4;
    const float* w0 = v_w + (size_t)(e0 + 0) * C_;
    const float* w1 = v_w + (size_t)(e0 + 1) * C_;
    const float* w2 = v_w + (size_t)(e0 + 2) * C_;
    const float* w3 = v_w + (size_t)(e0 + 3) * C_;
    float acc0 = 0.f, acc1 = 0.f, acc2 = 0.f, acc3 = 0.f;
    #pragma unroll
    for (int it = 0; it < 14; ++it) {
        int c = it * 32 + lane;
        float sv = s_sm[c];
        acc0 += w0[c] * sv;
        acc1 += w1[c] * sv;
        acc2 += w2[c] * sv;
        acc3 += w3[c] * sv;
    }
    #pragma unroll
    for (int o = 16; o > 0; o >>= 1) {
        acc0 += __shfl_down_sync(0xffffffffu, acc0, o);
        acc1 += __shfl_down_sync(0xffffffffu, acc1, o);
        acc2 += __shfl_down_sync(0xffffffffu, acc2, o);
        acc3 += __shfl_down_sync(0xffffffffu, acc3, o);
    }
    if (lane == 0) {
        g_pooled[b * E_ + e0 + 0] = acc0 * invD + v_b[e0 + 0];
        g_pooled[b * E_ + e0 + 1] = acc1 * invD + v_b[e0 + 1];
        g_pooled[b * E_ + e0 + 2] = acc2 * invD + v_b[e0 + 2];
        g_pooled[b * E_ + e0 + 3] = acc3 * invD + v_b[e0 + 3];
    }
}

// ============================================================
// Kernel 4: fused out-projection + residual. Barrier-free,
// streaming loads/stores (.cs) keep L2 for the hot tensors.
// ============================================================
__global__ void __launch_bounds__(256) k_residual(const float* __restrict__ img,
                                                  const float* __restrict__ o_w,
                                                  const float* __restrict__ o_b,
                                                  float* __restrict__ out)
{
    int blk = blockIdx.x;              // 0 .. B_*C_-1
    int b = blk / C_, c = blk - b * C_;
    int tid = threadIdx.x, lane = tid & 31;

    const float4* src = reinterpret_cast<const float4*>(img) + (size_t)blk * (N_ / 4);
    float4* dst = reinterpret_cast<float4*>(out) + (size_t)blk * (N_ / 4);

    // issue image loads first (784 float4: 3 per thread + 16-thread tail)
    float4 r0 = __ldcs(src + tid);
    float4 r1 = __ldcs(src + tid + 256);
    float4 r2 = __ldcs(src + tid + 512);
    float4 r3;
    if (tid < 16) r3 = __ldcs(src + tid + 768);

    // per-warp dot over e (o_w row + pooled row are cache-hot)
    const float* wr = o_w + (size_t)c * E_;
    const float* pl = g_pooled + b * E_;
    float p = 0.f;
    #pragma unroll
    for (int it = 0; it < 8; ++it) {
        int e = it * 32 + lane;
        p += wr[e] * pl[e];
    }
    #pragma unroll
    for (int o = 16; o > 0; o >>= 1) p += __shfl_xor_sync(0xffffffffu, p, o);
    float add = p + __ldg(&o_b[c]);

    r0.x += add; r0.y += add; r0.z += add; r0.w += add;
    r1.x += add; r1.y += add; r1.z += add; r1.w += add;
    r2.x += add; r2.y += add; r2.z += add; r2.w += add;
    __stcs(dst + tid, r0);
    __stcs(dst + tid + 256, r1);
    __stcs(dst + tid + 512, r2);
    if (tid < 16) {
        r3.x += add; r3.y += add; r3.z += add; r3.w += add;
        __stcs(dst + tid + 768, r3);
    }
}

// ============================================================
extern "C" void kernel_launch(void* const* d_in, const int* in_sizes, int n_in,
                              void* d_out, int out_size)
{
    const float* text = (const float*)d_in[0];
    const float* img  = (const float*)d_in[1];
    const float* q_w  = (const float*)d_in[2];
    const float* q_b  = (const float*)d_in[3];
    const float* k_w  = (const float*)d_in[4];
    const float* k_b  = (const float*)d_in[5];
    const float* v_w  = (const float*)d_in[6];
    const float* v_b  = (const float*)d_in[7];
    const float* o_w  = (const float*)d_in[8];
    const float* o_b  = (const float*)d_in[9];
    float* out = (float*)d_out;

    k_q<<<dim3(8, B_), 256>>>(text, q_w, q_b);
    k_a<<<B_, 256>>>(k_w, k_b);
    k_attn_pass<<<dim3(GX, B_), 256>>>(img);
    k_pool<<<dim3(B_, 8), 256>>>(v_w, v_b);
    k_residual<<<B_ * C_, 256>>>(img, o_w, o_b, out);
}

// round 9
// speedup vs baseline: 1.8412x; 1.0334x over previous
#include <cuda_runtime.h>
#include <cuda_bf16.h>
#include <cstdint>

// Problem shape (fixed by the dataset)
#define B_  32
#define T_  768
#define C_  448
#define E_  256
#define N_  3136          // H*W = 56*56
#define SCALE 0.0625f     // 1/sqrt(E)

#define CHUNK 16
#define GX 196                // pixel-groups per batch: 196*16 = 3136 exact

// -------- device scratch (no allocations allowed) --------
// All accumulators are zero on first use (static zero-init) and re-zeroed
// at the tail of k_residual for the next graph replay.
__device__ float g_a[B_ * C_];       // scale * (q[b]^T k_w)[c]   (atomic acc)
__device__ float g_qkb[B_];          // scale * q[b].k_b          (atomic acc)
__device__ float g_S[B_ * C_];       // attention-weighted channel sums (atomic)
__device__ float g_D[B_];            // exp-sum (atomic)
__device__ float g_pooled[B_ * E_];  // pooled (already /D, +v_b)

// ============================================================
// Kernel 1: fused q-projection + a-projection.
// grid (8, B_): block computes q[e] for its 32-e slice, then
// contributes partial a[b,c] and qkb[b] via atomicAdd.
// ============================================================
__global__ void __launch_bounds__(256) k_qa(
    const float* __restrict__ text, const float* __restrict__ q_w,
    const float* __restrict__ q_b,  const float* __restrict__ k_w,
    const float* __restrict__ k_b)
{
    int slice = blockIdx.x, b = blockIdx.y;
    int tid = threadIdx.x, warp = tid >> 5, lane = tid & 31;
    __shared__ float txt[T_];
    __shared__ float q_sm[32];

    const float4* tsrc = reinterpret_cast<const float4*>(text + (size_t)b * T_);
    for (int j = tid; j < T_ / 4; j += 256)
        reinterpret_cast<float4*>(txt)[j] = tsrc[j];
    __syncthreads();

    int eBase = slice * 32;
    {
        int e0 = eBase + warp * 4;
        const float4* tt = reinterpret_cast<const float4*>(txt);
        const float4* w0 = reinterpret_cast<const float4*>(q_w + (size_t)(e0 + 0) * T_);
        const float4* w1 = reinterpret_cast<const float4*>(q_w + (size_t)(e0 + 1) * T_);
        const float4* w2 = reinterpret_cast<const float4*>(q_w + (size_t)(e0 + 2) * T_);
        const float4* w3 = reinterpret_cast<const float4*>(q_w + (size_t)(e0 + 3) * T_);
        float a0 = 0.f, a1 = 0.f, a2 = 0.f, a3 = 0.f;
        #pragma unroll
        for (int it = 0; it < 6; ++it) {          // 6*32*4 = 768 exact
            int j = it * 32 + lane;
            float4 y = tt[j];
            float4 x0 = w0[j], x1 = w1[j], x2 = w2[j], x3 = w3[j];
            a0 += x0.x * y.x + x0.y * y.y + x0.z * y.z + x0.w * y.w;
            a1 += x1.x * y.x + x1.y * y.y + x1.z * y.z + x1.w * y.w;
            a2 += x2.x * y.x + x2.y * y.y + x2.z * y.z + x2.w * y.w;
            a3 += x3.x * y.x + x3.y * y.y + x3.z * y.z + x3.w * y.w;
        }
        #pragma unroll
        for (int o = 16; o > 0; o >>= 1) {
            a0 += __shfl_down_sync(0xffffffffu, a0, o);
            a1 += __shfl_down_sync(0xffffffffu, a1, o);
            a2 += __shfl_down_sync(0xffffffffu, a2, o);
            a3 += __shfl_down_sync(0xffffffffu, a3, o);
        }
        if (lane == 0) {
            q_sm[warp * 4 + 0] = a0 + q_b[e0 + 0];
            q_sm[warp * 4 + 1] = a1 + q_b[e0 + 1];
            q_sm[warp * 4 + 2] = a2 + q_b[e0 + 2];
            q_sm[warp * 4 + 3] = a3 + q_b[e0 + 3];
        }
    }
    __syncthreads();

    // qkb partial: one warp reduces this slice's 32 products
    if (warp == 0) {
        float p = q_sm[lane] * k_b[eBase + lane];
        #pragma unroll
        for (int o = 16; o > 0; o >>= 1) p += __shfl_xor_sync(0xffffffffu, p, o);
        if (lane == 0) atomicAdd(&g_qkb[b], SCALE * p);
    }

    // a[b,c] partial over this slice's 32 e-rows (k_w rows L2-hot across b)
    {
        int c0 = tid, c1 = tid + 256;       // c1 valid iff tid < 192
        float acc0 = 0.f, acc1 = 0.f;
        if (tid < 192) {
            #pragma unroll
            for (int j = 0; j < 32; ++j) {
                float qv = q_sm[j];
                const float* row = k_w + (size_t)(eBase + j) * C_;
                acc0 += qv * row[c0];
                acc1 += qv * row[c1];
            }
            atomicAdd(&g_a[b * C_ + c1], SCALE * acc1);
        } else {
            #pragma unroll
            for (int j = 0; j < 32; ++j)
                acc0 += q_sm[j] * k_w[(size_t)(eBase + j) * C_ + c0];
        }
        atomicAdd(&g_a[b * C_ + c0], SCALE * acc0);
    }
}

// ============================================================
// Kernel 2: all-register attention pass, one 16-pixel chunk per
// block. Thread layout: v = tid&3 (pixel quarter), k = tid>>2;
// thread owns channels it*64+k (it=0..6), pixels v*4..v*4+3.
// ============================================================
__global__ void __launch_bounds__(256) k_attn_pass(const float* __restrict__ img)
{
    int gx = blockIdx.x, b = blockIdx.y;
    int tid = threadIdx.x;
    int warp = tid >> 5, lane = tid & 31;
    int v = tid & 3, k = tid >> 2;

    __shared__ float a_sm[C_];
    __shared__ float red_s[128];        // [warp][16] partial logits
    __shared__ float e_sm[CHUNK];

    for (int c = tid; c < C_; c += 256) a_sm[c] = g_a[b * C_ + c];
    float qkb = g_qkb[b];

    // issue image loads immediately (independent of a_sm)
    const float* base = img + ((size_t)b * C_ + k) * N_ + gx * CHUNK + v * 4;
    float4 r[7];
    #pragma unroll
    for (int it = 0; it < 7; ++it)
        r[it] = __ldcs(reinterpret_cast<const float4*>(base + (size_t)(it * 64) * N_));
    __syncthreads();

    // per-thread a values for its 7 channels
    float aq[7];
    #pragma unroll
    for (int it = 0; it < 7; ++it) aq[it] = a_sm[it * 64 + k];

    // ---- phase A partials from registers (28 FMA) ----
    float plx = 0.f, ply = 0.f, plz = 0.f, plw = 0.f;
    #pragma unroll
    for (int it = 0; it < 7; ++it) {
        float a = aq[it];
        plx += a * r[it].x; ply += a * r[it].y;
        plz += a * r[it].z; plw += a * r[it].w;
    }

    // ---- reduce partials over lanes sharing v (strides 4,8,16) ----
    #pragma unroll
    for (int m = 4; m <= 16; m <<= 1) {
        plx += __shfl_xor_sync(0xffffffffu, plx, m);
        ply += __shfl_xor_sync(0xffffffffu, ply, m);
        plz += __shfl_xor_sync(0xffffffffu, plz, m);
        plw += __shfl_xor_sync(0xffffffffu, plw, m);
    }
    if (lane < 4) {      // lane == v for lanes 0..3
        float4 p4 = make_float4(plx, ply, plz, plw);
        reinterpret_cast<float4*>(red_s)[warp * 4 + lane] = p4;
    }
    __syncthreads();

    // ---- exp over 16 pixels + D flush ----
    if (tid < 16) {
        float lg = 0.f;
        #pragma unroll
        for (int w = 0; w < 8; ++w) lg += red_s[w * 16 + tid];
        float e = __expf(lg + qkb);
        e_sm[tid] = e;
        float d = e;
        d += __shfl_xor_sync(0xffffu, d, 8);
        d += __shfl_xor_sync(0xffffu, d, 4);
        d += __shfl_xor_sync(0xffffu, d, 2);
        d += __shfl_xor_sync(0xffffu, d, 1);
        if (tid == 0) atomicAdd(&g_D[b], d);
    }
    __syncthreads();

    // ---- phase B from registers (28 FMA) + flush ----
    float4 e4 = reinterpret_cast<const float4*>(e_sm)[v];
    #pragma unroll
    for (int it = 0; it < 7; ++it) {
        float s = r[it].x * e4.x + r[it].y * e4.y
                + r[it].z * e4.z + r[it].w * e4.w;
        s += __shfl_xor_sync(0xffffffffu, s, 1);
        s += __shfl_xor_sync(0xffffffffu, s, 2);
        if (v == 0) atomicAdd(&g_S[b * C_ + it * 64 + k], s);
    }
}

// ============================================================
// Kernel 3: pooled = v_w @ (g_S/D) + v_b.
// grid (B_, 8): warp-per-4e, one trip; g_S is tiny & L2-hot.
// ============================================================
__global__ void __launch_bounds__(256) k_pool(
    const float* __restrict__ v_w, const float* __restrict__ v_b)
{
    int b = blockIdx.x, slice = blockIdx.y;
    int tid = threadIdx.x, warp = tid >> 5, lane = tid & 31;
    __shared__ float s_sm[C_];
    __shared__ float invD_sm;

    s_sm[tid] = g_S[b * C_ + tid];
    if (tid < C_ - 256) s_sm[tid + 256] = g_S[b * C_ + tid + 256];
    if (tid == 0) invD_sm = 1.0f / g_D[b];
    __syncthreads();
    float invD = invD_sm;

    int e0 = slice * 32 + warp * 4;
    const float* w0 = v_w + (size_t)(e0 + 0) * C_;
    const float* w1 = v_w + (size_t)(e0 + 1) * C_;
    const float* w2 = v_w + (size_t)(e0 + 2) * C_;
    const float* w3 = v_w + (size_t)(e0 + 3) * C_;
    float acc0 = 0.f, acc1 = 0.f, acc2 = 0.f, acc3 = 0.f;
    #pragma unroll
    for (int it = 0; it < 14; ++it) {
        int c = it * 32 + lane;
        float sv = s_sm[c];
        acc0 += w0[c] * sv;
        acc1 += w1[c] * sv;
        acc2 += w2[c] * sv;
        acc3 += w3[c] * sv;
    }
    #pragma unroll
    for (int o = 16; o > 0; o >>= 1) {
        acc0 += __shfl_down_sync(0xffffffffu, acc0, o);
        acc1 += __shfl_down_sync(0xffffffffu, acc1, o);
        acc2 += __shfl_down_sync(0xffffffffu, acc2, o);
        acc3 += __shfl_down_sync(0xffffffffu, acc3, o);
    }
    if (lane == 0) {
        g_pooled[b * E_ + e0 + 0] = acc0 * invD + v_b[e0 + 0];
        g_pooled[b * E_ + e0 + 1] = acc1 * invD + v_b[e0 + 1];
        g_pooled[b * E_ + e0 + 2] = acc2 * invD + v_b[e0 + 2];
        g_pooled[b * E_ + e0 + 3] = acc3 * invD + v_b[e0 + 3];
    }
}

// ============================================================
// Kernel 4: fused out-projection + residual. Barrier-free,
// streaming loads/stores. Tail: re-zero accumulators for the
// next graph replay (grid == B_*C_ covers every element).
// ============================================================
__global__ void __launch_bounds__(256) k_residual(const float* __restrict__ img,
                                                  const float* __restrict__ o_w,
                                                  const float* __restrict__ o_b,
                                                  float* __restrict__ out)
{
    int blk = blockIdx.x;              // 0 .. B_*C_-1
    int b = blk / C_, c = blk - b * C_;
    int tid = threadIdx.x, lane = tid & 31;

    const float4* src = reinterpret_cast<const float4*>(img) + (size_t)blk * (N_ / 4);
    float4* dst = reinterpret_cast<float4*>(out) + (size_t)blk * (N_ / 4);

    // issue image loads first (784 float4: 3 per thread + 16-thread tail)
    float4 r0 = __ldcs(src + tid);
    float4 r1 = __ldcs(src + tid + 256);
    float4 r2 = __ldcs(src + tid + 512);
    float4 r3;
    if (tid < 16) r3 = __ldcs(src + tid + 768);

    // per-warp dot over e (o_w row + pooled row are cache-hot)
    const float* wr = o_w + (size_t)c * E_;
    const float* pl = g_pooled + b * E_;
    float p = 0.f;
    #pragma unroll
    for (int it = 0; it < 8; ++it) {
        int e = it * 32 + lane;
        p += wr[e] * pl[e];
    }
    #pragma unroll
    for (int o = 16; o > 0; o >>= 1) p += __shfl_xor_sync(0xffffffffu, p, o);
    float add = p + __ldg(&o_b[c]);

    // re-zero accumulators for the next replay (one element per block)
    if (tid == 64) {
        g_a[blk] = 0.f;
        g_S[blk] = 0.f;
        if (blk < B_) { g_qkb[blk] = 0.f; g_D[blk] = 0.f; }
    }

    r0.x += add; r0.y += add; r0.z += add; r0.w += add;
    r1.x += add; r1.y += add; r1.z += add; r1.w += add;
    r2.x += add; r2.y += add; r2.z += add; r2.w += add;
    __stcs(dst + tid, r0);
    __stcs(dst + tid + 256, r1);
    __stcs(dst + tid + 512, r2);
    if (tid < 16) {
        r3.x += add; r3.y += add; r3.z += add; r3.w += add;
        __stcs(dst + tid + 768, r3);
    }
}

// ============================================================
extern "C" void kernel_launch(void* const* d_in, const int* in_sizes, int n_in,
                              void* d_out, int out_size)
{
    const float* text = (const float*)d_in[0];
    const float* img  = (const float*)d_in[1];
    const float* q_w  = (const float*)d_in[2];
    const float* q_b  = (const float*)d_in[3];
    const float* k_w  = (const float*)d_in[4];
    const float* k_b  = (const float*)d_in[5];
    const float* v_w  = (const float*)d_in[6];
    const float* v_b  = (const float*)d_in[7];
    const float* o_w  = (const float*)d_in[8];
    const float* o_b  = (const float*)d_in[9];
    float* out = (float*)d_out;

    k_qa<<<dim3(8, B_), 256>>>(text, q_w, q_b, k_w, k_b);
    k_attn_pass<<<dim3(GX, B_), 256>>>(img);
    k_pool<<<dim3(B_, 8), 256>>>(v_w, v_b);
    k_residual<<<B_ * C_, 256>>>(img, o_w, o_b, out);
}